// round 15
// baseline (speedup 1.0000x reference)
#include <cuda_runtime.h>
#include <cstdint>
#include <cfloat>
#include <math.h>

#define B_ 8
#define N_ 16384
#define NPOINT_ 1024
#define K_ 32
#define SAMPLE_NUM_ 10
#define SEL_ 7
#define SUBSET_ 29
#define RADIUS_ 0.2f

#define CLUSTER_ 16                   // nonportable cluster size (runtime-configured)
#define SLICE_ (N_ / CLUSTER_)        // 1024 points per FPS CTA
#define FPS_T_ 256
#define PPT_ (SLICE_ / FPS_T_)        // 4 points per thread
#define FPS_CTAS_ (B_ * CLUSTER_)     // 128

#define CTILE_ 4                      // centers per knn CTA
#define KNN_TILES_ (NPOINT_ / CTILE_) // 256 tiles per batch

// FPS-selected center coordinates (B, NPOINT, 3)
__device__ float g_centers[B_ * NPOINT_ * 3];
// Packed points: (x, y, z, xx) with xx = ((x*x+y*y)+z*z) reference-rounded
__device__ float4 g_pts[B_ * N_];

struct Perms { unsigned char p[SAMPLE_NUM_][SUBSET_]; };

__device__ __forceinline__ unsigned smem_u32(const void* p) {
    unsigned a;
    asm("{ .reg .u64 t; cvta.to.shared.u64 t, %1; cvt.u32.u64 %0, t; }"
        : "=r"(a) : "l"(p));
    return a;
}

// ======================= Kernel A: 16-CTA-cluster FPS =======================
// Each CTA owns a 1024-pt slice in registers (coords in smem for winner
// lookup). Per iteration: register distance update (PPT=4, ~half the per-SM
// issue load of csz=8) -> REDUX warp argmax -> 8-slot CTA scan -> 16 parallel
// DSMEM candidate sends -> one cluster barrier -> 16-slot winner pick.
// Packed (dist_bits<<32 | ~idx) max reproduces jnp.argmax first-index ties.
__global__ void __launch_bounds__(FPS_T_)
fps_cluster_kernel(const float* __restrict__ xyz)
{
    __shared__ float ox[SLICE_], oy[SLICE_], oz[SLICE_];
    __shared__ unsigned long long warr[FPS_T_ / 32];
    __shared__ unsigned long long skey[2][CLUSTER_];
    __shared__ float scx[2][CLUSTER_], scy[2][CLUSTER_], scz[2][CLUSTER_];

    const int t = threadIdx.x;
    unsigned rank;
    asm("mov.u32 %0, %%cluster_ctarank;" : "=r"(rank));
    const int b = blockIdx.x / CLUSTER_;
    const int base = (int)rank * SLICE_;
    const float* X = xyz + (size_t)b * N_ * 3;

    float px[PPT_], py[PPT_], pz[PPT_], dd[PPT_];
#pragma unroll
    for (int k = 0; k < PPT_; k++) {
        int l = (k << 8) + t;          // local index in slice
        int n = base + l;
        float x = X[n * 3 + 0], y = X[n * 3 + 1], z = X[n * 3 + 2];
        px[k] = x; py[k] = y; pz[k] = z;
        ox[l] = x; oy[l] = y; oz[l] = z;
        dd[k] = 1e10f;
        float xx = __fadd_rn(__fadd_rn(__fmul_rn(x, x), __fmul_rn(y, y)),
                             __fmul_rn(z, z));
        g_pts[(size_t)b * N_ + n] = make_float4(x, y, z, xx);
    }
    __syncthreads();

    // initial centroid = point 0 (reference starts farthest=0)
    float cx = X[0], cy = X[1], cz = X[2];
    float* outc = g_centers + (size_t)b * NPOINT_ * 3;

    for (int s = 0; s < NPOINT_; s++) {
        if (rank == 0 && t == 0) {
            outc[s * 3 + 0] = cx; outc[s * 3 + 1] = cy; outc[s * 3 + 2] = cz;
        }
        if (s == NPOINT_ - 1) break;   // last center stored; exchange is dead work
        const int par = s & 1;

        // per-thread argmax (strict > keeps first index; n ascending in k)
        float maxd = -1.0f; int bi = 0;
#pragma unroll
        for (int k = 0; k < PPT_; k++) {
            int n = base + (k << 8) + t;
            // match XLA: ((dx*dx + dy*dy) + dz*dz), each op rounded, no FMA
            float dx = __fsub_rn(px[k], cx);
            float dy = __fsub_rn(py[k], cy);
            float dz = __fsub_rn(pz[k], cz);
            float d  = __fadd_rn(__fadd_rn(__fmul_rn(dx, dx), __fmul_rn(dy, dy)),
                                 __fmul_rn(dz, dz));
            float nd = fminf(dd[k], d);
            dd[k] = nd;
            if (nd > maxd) { maxd = nd; bi = n; }
        }
        // warp argmax via REDUX: dist bits (>=0, monotone), then ~idx among matches
        unsigned hb = __float_as_uint(maxd);
        unsigned mh = __reduce_max_sync(0xffffffffu, hb);
        unsigned cd = (hb == mh) ? ~(unsigned)bi : 0u;
        unsigned ml = __reduce_max_sync(0xffffffffu, cd);
        if ((t & 31) == 0)
            warr[t >> 5] = ((unsigned long long)mh << 32) | ml;
        __syncthreads();

        // threads 0..15: CTA-best over 8 warp slots, then send to cluster CTA t
        if (t < CLUSTER_) {
            unsigned long long bb = warr[0];
#pragma unroll
            for (int w = 1; w < FPS_T_ / 32; w++) {
                unsigned long long v = warr[w];
                bb = (v > bb) ? v : bb;
            }
            int g = (int)(~(unsigned)(bb & 0xffffffffu));
            int l = g - base;
            float wx = ox[l], wy = oy[l], wz = oz[l];
            unsigned a_key = smem_u32(&skey[par][rank]);
            unsigned a_cx  = smem_u32(&scx[par][rank]);
            unsigned a_cy  = smem_u32(&scy[par][rank]);
            unsigned a_cz  = smem_u32(&scz[par][rank]);
            unsigned r_key, r_cx, r_cy, r_cz;
            asm("mapa.shared::cluster.u32 %0, %1, %2;" : "=r"(r_key) : "r"(a_key), "r"(t));
            asm("mapa.shared::cluster.u32 %0, %1, %2;" : "=r"(r_cx)  : "r"(a_cx),  "r"(t));
            asm("mapa.shared::cluster.u32 %0, %1, %2;" : "=r"(r_cy)  : "r"(a_cy),  "r"(t));
            asm("mapa.shared::cluster.u32 %0, %1, %2;" : "=r"(r_cz)  : "r"(a_cz),  "r"(t));
            asm volatile("st.shared::cluster.b64 [%0], %1;" :: "r"(r_key), "l"(bb) : "memory");
            asm volatile("st.shared::cluster.b32 [%0], %1;" :: "r"(r_cx), "r"(__float_as_uint(wx)) : "memory");
            asm volatile("st.shared::cluster.b32 [%0], %1;" :: "r"(r_cy), "r"(__float_as_uint(wy)) : "memory");
            asm volatile("st.shared::cluster.b32 [%0], %1;" :: "r"(r_cz), "r"(__float_as_uint(wz)) : "memory");
        }

        // one cluster barrier per iteration (release orders the DSMEM stores)
        asm volatile("barrier.cluster.arrive.aligned;" ::: "memory");
        asm volatile("barrier.cluster.wait.aligned;" ::: "memory");

        // winner among the 16 slots (broadcast LDS; parity protects slot reuse)
        unsigned long long w0 = skey[par][0];
        int wi = 0;
#pragma unroll
        for (int r = 1; r < CLUSTER_; r++) {
            unsigned long long v = skey[par][r];
            if (v > w0) { w0 = v; wi = r; }
        }
        cx = scx[par][wi]; cy = scy[par][wi]; cz = scz[par][wi];
    }
}

// ======================= Kernel B: tiled KNN + robust centroid + features (R9) =============
__global__ __launch_bounds__(256, 4) void knn_feat_kernel(float* __restrict__ out,
                                                          Perms perms)
{
    __shared__ unsigned long long cand[CTILE_][256][4];   // 32KB
    __shared__ unsigned long long heads[CTILE_][256];     // 8KB, transposed slots
    __shared__ unsigned char curs[CTILE_][256];
    __shared__ int nb[CTILE_][K_];
    __shared__ float gx[CTILE_][K_], gy[CTILE_][K_], gz[CTILE_][K_];
    __shared__ float cdv[CTILE_][SAMPLE_NUM_][3];

    const int bid = blockIdx.x;
    const int b = bid / KNN_TILES_;
    const int tile = bid % KNN_TILES_;
    const int s0 = tile * CTILE_;
    const int t = threadIdx.x;
    const float4* P = g_pts + (size_t)b * N_;

    float ccx[CTILE_], ccy[CTILE_], ccz[CTILE_], ccc[CTILE_];
#pragma unroll
    for (int c = 0; c < CTILE_; c++) {
        int bs = b * NPOINT_ + s0 + c;
        float x = g_centers[bs * 3 + 0];
        float y = g_centers[bs * 3 + 1];
        float z = g_centers[bs * 3 + 2];
        ccx[c] = x; ccy[c] = y; ccz[c] = z;
        ccc[c] = __fadd_rn(__fadd_rn(__fmul_rn(x, x), __fmul_rn(y, y)),
                           __fmul_rn(z, z));
    }

    // exact sorted top-4 per thread per center (strict < keeps first index;
    // n ascending within thread; d2 never -0.0 under RN)
    float v0[CTILE_], v1[CTILE_], v2[CTILE_], v3[CTILE_];
    int i0[CTILE_], i1[CTILE_], i2[CTILE_], i3[CTILE_];
#pragma unroll
    for (int c = 0; c < CTILE_; c++) {
        v0[c] = v1[c] = v2[c] = v3[c] = FLT_MAX;
        i0[c] = i1[c] = i2[c] = i3[c] = 0;
    }
#pragma unroll 4
    for (int k = 0; k < 64; k++) {
        int n = t + (k << 8);
        float4 p = __ldg(&P[n]);
#pragma unroll
        for (int c = 0; c < CTILE_; c++) {
            float dt = __fadd_rn(__fadd_rn(__fmul_rn(ccx[c], p.x), __fmul_rn(ccy[c], p.y)),
                                 __fmul_rn(ccz[c], p.z));
            // match reference: (cc + xx) - 2*dot
            float d2 = __fsub_rn(__fadd_rn(ccc[c], p.w), __fmul_rn(2.0f, dt));
            if (d2 < v3[c]) {
                if (d2 < v2[c]) {
                    v3[c] = v2[c]; i3[c] = i2[c];
                    if (d2 < v1[c]) {
                        v2[c] = v1[c]; i2[c] = i1[c];
                        if (d2 < v0[c]) { v1[c] = v0[c]; i1[c] = i0[c]; v0[c] = d2; i0[c] = n; }
                        else             { v1[c] = d2; i1[c] = n; }
                    } else { v2[c] = d2; i2[c] = n; }
                } else { v3[c] = d2; i3[c] = n; }
            }
        }
    }
    auto pack = [](float v, int n) -> unsigned long long {
        unsigned fb = __float_as_uint(v);
        fb = (fb & 0x80000000u) ? ~fb : (fb | 0x80000000u);   // monotone map
        return ((unsigned long long)fb << 32) | (unsigned)n;
    };
    const int hslot = (t & 7) * 32 + (t >> 3);   // transposed heads slot
#pragma unroll
    for (int c = 0; c < CTILE_; c++) {
        unsigned long long k0 = pack(v0[c], i0[c]);
        cand[c][t][0] = k0;
        cand[c][t][1] = pack(v1[c], i1[c]);
        cand[c][t][2] = pack(v2[c], i2[c]);
        cand[c][t][3] = pack(v3[c], i3[c]);
        heads[c][hslot] = k0;
        curs[c][t] = 0;
    }
    __syncthreads();

    const int wid = t >> 5;
    const int lane = t & 31;
    if (wid < CTILE_) {
        const int c = wid;
        for (int j = 0; j < K_; j++) {
            unsigned long long lm = heads[c][lane]; int li = 0;
#pragma unroll
            for (int i = 1; i < 8; i++) {
                unsigned long long v = heads[c][i * 32 + lane];
                if (v < lm) { lm = v; li = i; }
            }
            unsigned hi = (unsigned)(lm >> 32), lo = (unsigned)lm;
            unsigned mh = __reduce_min_sync(0xffffffffu, hi);
            unsigned cl = (hi == mh) ? lo : 0xffffffffu;
            unsigned ml = __reduce_min_sync(0xffffffffu, cl);
            unsigned long long w = ((unsigned long long)mh << 32) | ml;
            if (lane == 0) nb[c][j] = (int)ml;
            if (lm == w) {                       // unique owner lane
                int T = lane * 8 + li;
                int cur = (int)curs[c][T] + 1;
                curs[c][T] = (unsigned char)cur;
                unsigned long long nh;
                if (cur < 4) {
                    nh = cand[c][T][cur];
                } else {
                    // exact refill: min key > w over T's 64 points (rare)
                    nh = 0xFFFFFFFFFFFFFFFFull;
                    for (int k = 0; k < 64; k++) {
                        int n = T + (k << 8);
                        float4 p = __ldg(&P[n]);
                        float dt = __fadd_rn(__fadd_rn(__fmul_rn(ccx[c], p.x), __fmul_rn(ccy[c], p.y)),
                                             __fmul_rn(ccz[c], p.z));
                        float d2 = __fsub_rn(__fadd_rn(ccc[c], p.w), __fmul_rn(2.0f, dt));
                        unsigned fb = __float_as_uint(d2);
                        fb = (fb & 0x80000000u) ? ~fb : (fb | 0x80000000u);
                        unsigned long long pk = ((unsigned long long)fb << 32) | (unsigned)n;
                        if (pk > w && pk < nh) nh = pk;
                    }
                }
                heads[c][li * 32 + lane] = nh;
            }
        }
        __syncwarp();

        {
            int n = nb[c][lane];
            float4 p = __ldg(&P[n]);
            gx[c][lane] = p.x; gy[c][lane] = p.y; gz[c][lane] = p.z;
        }
        __syncwarp();

        if (lane < SAMPLE_NUM_) {
            float ax = 0.f, ay = 0.f, az = 0.f;
            for (int j = 0; j < SUBSET_; j++) {
                int p = perms.p[lane][j];
                ax += gx[c][p]; ay += gy[c][p]; az += gz[c][p];
            }
            cdv[c][lane][0] = ax / (float)SUBSET_;
            cdv[c][lane][1] = ay / (float)SUBSET_;
            cdv[c][lane][2] = az / (float)SUBSET_;
        }
        __syncwarp();

        if (lane == 0) {
            float sq[SAMPLE_NUM_], ps[SAMPLE_NUM_];
            for (int j = 0; j < SAMPLE_NUM_; j++)
                sq[j] = cdv[c][j][0] * cdv[c][j][0] + cdv[c][j][1] * cdv[c][j][1]
                      + cdv[c][j][2] * cdv[c][j][2];
            for (int j = 0; j < SAMPLE_NUM_; j++) {
                float acc = 0.f;
                for (int k2 = 0; k2 < SAMPLE_NUM_; k2++) {
                    float dt = cdv[c][j][0] * cdv[c][k2][0] + cdv[c][j][1] * cdv[c][k2][1]
                             + cdv[c][j][2] * cdv[c][k2][2];
                    acc += sq[j] + sq[k2] - 2.0f * dt;
                }
                ps[j] = acc;
            }
            bool used[SAMPLE_NUM_];
            for (int j = 0; j < SAMPLE_NUM_; j++) used[j] = false;
            float mx = 0.f, my = 0.f, mz = 0.f;
            for (int r = 0; r < SEL_; r++) {
                int bsel = 0; float bv = FLT_MAX;
                for (int k2 = 0; k2 < SAMPLE_NUM_; k2++)
                    if (!used[k2] && ps[k2] < bv) { bv = ps[k2]; bsel = k2; }
                used[bsel] = true;
                mx += cdv[c][bsel][0]; my += cdv[c][bsel][1]; mz += cdv[c][bsel][2];
            }
            mx /= (float)SEL_; my /= (float)SEL_; mz /= (float)SEL_;

            float cx = ccx[c], cy = ccy[c], cz = ccz[c];
            float ref_norm = sqrtf(cx * cx + cy * cy + cz * cz);
            float den = ref_norm + 1e-4f;
            float ux = cx / den, uy = cy / den, uz = cz / den;
            float ix = RADIUS_ * ux + cx, iy = RADIUS_ * uy + cy, iz = RADIUS_ * uz + cz;

            float crx = cx - mx, cry = cy - my, crz = cz - mz;
            float crd = sqrtf(crx * crx + cry * cry + crz * crz);
            float cvx = ix - mx, cvy = iy - my, cvz = iz - mz;
            float cid = sqrtf(cvx * cvx + cvy * cvy + cvz * cvz);
            float dot = crx * cvx + cry * cvy + crz * cvz;
            float ang_rci = dot / (crd * cid + 1e-6f);

            float irx = cx - ix, iry = cy - iy, irz = cz - iz;
            float icx = mx - ix, icy = my - iy, icz = mz - iz;
            float dot2 = irx * icx + iry * icy + irz * icz;
            float ang_ric = dot2 / (RADIUS_ * cid + 1e-6f);

            int bs = b * NPOINT_ + s0 + c;
            float* o = out + (size_t)bs * 5;
            o[0] = ref_norm; o[1] = crd; o[2] = cid; o[3] = ang_rci; o[4] = ang_ric;
        }
    }
}

// ======================= Host: threefry-2x32 (JAX partitionable PRNG) =======================
static inline uint32_t rotl32_(uint32_t x, int r) { return (x << r) | (x >> (32 - r)); }

static void tf2x32_(uint32_t k0, uint32_t k1, uint32_t x0, uint32_t x1,
                    uint32_t& o0, uint32_t& o1)
{
    static const int R0[4] = {13, 15, 26, 6};
    static const int R1[4] = {17, 29, 16, 24};
    uint32_t ks[3] = {k0, k1, k0 ^ k1 ^ 0x1BD11BDAu};
    x0 += ks[0]; x1 += ks[1];
    for (int i = 0; i < 5; i++) {
        const int* R = (i & 1) ? R1 : R0;
        for (int j = 0; j < 4; j++) { x0 += x1; x1 = rotl32_(x1, R[j]); x1 ^= x0; }
        x0 += ks[(i + 1) % 3];
        x1 += ks[(i + 2) % 3] + (uint32_t)(i + 1);
    }
    o0 = x0; o1 = x1;
}

// jax.random.permutation(fold_in(key(42), i), 32)[:29], threefry partitionable mode.
static void make_perms(unsigned char p[SAMPLE_NUM_][SUBSET_])
{
    for (int i = 0; i < SAMPLE_NUM_; i++) {
        uint32_t k0, k1, s0, s1;
        tf2x32_(0u, 42u, 0u, (uint32_t)i, k0, k1);     // fold_in
        tf2x32_(k0, k1, 0u, 1u, s0, s1);               // split -> subkey (index 1)
        uint32_t bits[K_];
        for (int j = 0; j < K_; j++) {
            uint32_t hi, lo;
            tf2x32_(s0, s1, 0u, (uint32_t)j, hi, lo);
            bits[j] = hi ^ lo;                         // 32-bit path XORs both words
        }
        int idx[K_];
        for (int j = 0; j < K_; j++) idx[j] = j;
        for (int a = 1; a < K_; a++) {                 // stable insertion sort
            uint32_t bv = bits[a]; int iv = idx[a]; int c = a - 1;
            while (c >= 0 && bits[c] > bv) {
                bits[c + 1] = bits[c]; idx[c + 1] = idx[c]; c--;
            }
            bits[c + 1] = bv; idx[c + 1] = iv;
        }
        for (int j = 0; j < SUBSET_; j++) p[i][j] = (unsigned char)idx[j];
    }
}

extern "C" void kernel_launch(void* const* d_in, const int* in_sizes, int n_in,
                              void* d_out, int out_size)
{
    (void)in_sizes; (void)n_in; (void)out_size;
    const float* xyz = (const float*)d_in[0];
    float* out = (float*)d_out;

    Perms perms;
    make_perms(perms.p);   // deterministic, cheap, every call

    // 16-CTA clusters: nonportable size, configured at launch
    cudaFuncSetAttribute(fps_cluster_kernel,
                         cudaFuncAttributeNonPortableClusterSizeAllowed, 1);

    cudaLaunchConfig_t cfg = {};
    cfg.gridDim = dim3(FPS_CTAS_, 1, 1);
    cfg.blockDim = dim3(FPS_T_, 1, 1);
    cfg.dynamicSmemBytes = 0;
    cfg.stream = 0;
    cudaLaunchAttribute attrs[1];
    attrs[0].id = cudaLaunchAttributeClusterDimension;
    attrs[0].val.clusterDim.x = CLUSTER_;
    attrs[0].val.clusterDim.y = 1;
    attrs[0].val.clusterDim.z = 1;
    cfg.attrs = attrs;
    cfg.numAttrs = 1;
    cudaLaunchKernelEx(&cfg, fps_cluster_kernel, xyz);

    knn_feat_kernel<<<B_ * KNN_TILES_, 256>>>(out, perms);
}

// round 16
// speedup vs baseline: 1.5068x; 1.5068x over previous
#include <cuda_runtime.h>
#include <cstdint>
#include <cfloat>
#include <math.h>

#define B_ 8
#define N_ 16384
#define NPOINT_ 1024
#define K_ 32
#define SAMPLE_NUM_ 10
#define SEL_ 7
#define SUBSET_ 29
#define RADIUS_ 0.2f

#define CLUSTER_ 8
#define SLICE_ (N_ / CLUSTER_)        // 2048 points per FPS CTA
#define FPS_T_ 256
#define PPT_ (SLICE_ / FPS_T_)        // 8 points per thread (4 f32x2 pairs)

#define CTILE_ 4                      // centers per knn CTA
#define KNN_TILES_ (NPOINT_ / CTILE_) // 256 tiles per batch

// FPS-selected center coordinates (B, NPOINT, 3)
__device__ float g_centers[B_ * NPOINT_ * 3];
// Packed points: (x, y, z, xx) with xx = ((x*x+y*y)+z*z) reference-rounded
__device__ float4 g_pts[B_ * N_];

struct Perms { unsigned char p[SAMPLE_NUM_][SUBSET_]; };

__device__ __forceinline__ unsigned smem_u32(const void* p) {
    unsigned a;
    asm("{ .reg .u64 t; cvta.to.shared.u64 t, %1; cvt.u32.u64 %0, t; }"
        : "=r"(a) : "l"(p));
    return a;
}
// ---- packed f32x2 helpers (two independent RN ops == scalar __f*_rn) ----
__device__ __forceinline__ unsigned long long pk2(float a, float b) {
    unsigned long long r;
    asm("mov.b64 %0, {%1, %2};" : "=l"(r) : "f"(a), "f"(b));
    return r;
}
__device__ __forceinline__ void up2(unsigned long long v, float& a, float& b) {
    asm("mov.b64 {%0, %1}, %2;" : "=f"(a), "=f"(b) : "l"(v));
}
__device__ __forceinline__ unsigned long long add2(unsigned long long a, unsigned long long b) {
    unsigned long long r;
    asm("add.rn.f32x2 %0, %1, %2;" : "=l"(r) : "l"(a), "l"(b));
    return r;
}
__device__ __forceinline__ unsigned long long mul2(unsigned long long a, unsigned long long b) {
    unsigned long long r;
    asm("mul.rn.f32x2 %0, %1, %2;" : "=l"(r) : "l"(a), "l"(b));
    return r;
}

// ======================= Kernel A: cluster-parallel FPS (R9 topology + f32x2) ==============
// One 8-CTA cluster per batch (proven optimum). Points in packed f32x2 register
// pairs; distances via add/mul.rn.f32x2 (bit-identical to scalar __f*_rn chain:
// x-c == x+(-c), each lane independently RN-rounded). REDUX warp argmax;
// sender-only CTA-best scan; DSMEM exchange + one cluster barrier per iteration.
// Packed (dist_bits<<32 | ~idx) max reproduces jnp.argmax first-index ties.
__global__ __launch_bounds__(FPS_T_) __cluster_dims__(CLUSTER_, 1, 1)
void fps_cluster_kernel(const float* __restrict__ xyz)
{
    __shared__ float ox[SLICE_], oy[SLICE_], oz[SLICE_];
    __shared__ unsigned long long warr[FPS_T_ / 32];
    __shared__ unsigned long long skey[2][CLUSTER_];
    __shared__ float scx[2][CLUSTER_], scy[2][CLUSTER_], scz[2][CLUSTER_];

    const int t = threadIdx.x;
    unsigned rank;
    asm("mov.u32 %0, %%cluster_ctarank;" : "=r"(rank));
    const int b = blockIdx.x >> 3;
    const int base = (int)rank * SLICE_;
    const float* X = xyz + (size_t)b * N_ * 3;

    unsigned long long px2[PPT_ / 2], py2[PPT_ / 2], pz2[PPT_ / 2];
    float dd[PPT_];
#pragma unroll
    for (int k = 0; k < PPT_; k += 2) {
        int l0 = (k << 8) + t;
        int l1 = ((k + 1) << 8) + t;
        int n0 = base + l0, n1 = base + l1;
        float x0 = X[n0 * 3 + 0], y0 = X[n0 * 3 + 1], z0 = X[n0 * 3 + 2];
        float x1 = X[n1 * 3 + 0], y1 = X[n1 * 3 + 1], z1 = X[n1 * 3 + 2];
        ox[l0] = x0; oy[l0] = y0; oz[l0] = z0;
        ox[l1] = x1; oy[l1] = y1; oz[l1] = z1;
        px2[k >> 1] = pk2(x0, x1);
        py2[k >> 1] = pk2(y0, y1);
        pz2[k >> 1] = pk2(z0, z1);
        dd[k] = 1e10f; dd[k + 1] = 1e10f;
        float xx0 = __fadd_rn(__fadd_rn(__fmul_rn(x0, x0), __fmul_rn(y0, y0)),
                              __fmul_rn(z0, z0));
        float xx1 = __fadd_rn(__fadd_rn(__fmul_rn(x1, x1), __fmul_rn(y1, y1)),
                              __fmul_rn(z1, z1));
        g_pts[(size_t)b * N_ + n0] = make_float4(x0, y0, z0, xx0);
        g_pts[(size_t)b * N_ + n1] = make_float4(x1, y1, z1, xx1);
    }
    __syncthreads();

    // initial centroid = point 0 (reference starts farthest=0)
    float cx = X[0], cy = X[1], cz = X[2];
    float* outc = g_centers + (size_t)b * NPOINT_ * 3;

    for (int s = 0; s < NPOINT_; s++) {
        if (rank == 0 && t == 0) {
            outc[s * 3 + 0] = cx; outc[s * 3 + 1] = cy; outc[s * 3 + 2] = cz;
        }
        if (s == NPOINT_ - 1) break;   // last center stored; exchange is dead work
        const int par = s & 1;

        // packed negated center (negation exact; x+(-c) == RN(x-c))
        const unsigned long long ncx2 = pk2(-cx, -cx);
        const unsigned long long ncy2 = pk2(-cy, -cy);
        const unsigned long long ncz2 = pk2(-cz, -cz);

        // per-thread argmax (strict > keeps first index; n ascending in k)
        float maxd = -1.0f; int bi = 0;
#pragma unroll
        for (int k = 0; k < PPT_; k += 2) {
            int n0 = base + (k << 8) + t;
            int n1 = n0 + 256;
            // d = ((dx*dx + dy*dy) + dz*dz), each lane RN-rounded (matches XLA)
            unsigned long long dx2 = add2(px2[k >> 1], ncx2);
            unsigned long long dy2 = add2(py2[k >> 1], ncy2);
            unsigned long long dz2 = add2(pz2[k >> 1], ncz2);
            unsigned long long d2p = add2(add2(mul2(dx2, dx2), mul2(dy2, dy2)),
                                          mul2(dz2, dz2));
            float d0, d1;
            up2(d2p, d0, d1);
            float nd0 = fminf(dd[k], d0);     dd[k] = nd0;
            if (nd0 > maxd) { maxd = nd0; bi = n0; }
            float nd1 = fminf(dd[k + 1], d1); dd[k + 1] = nd1;
            if (nd1 > maxd) { maxd = nd1; bi = n1; }
        }
        // warp argmax via REDUX: dist bits (>=0, monotone), then ~idx among matches
        unsigned hb = __float_as_uint(maxd);
        unsigned mh = __reduce_max_sync(0xffffffffu, hb);
        unsigned cd = (hb == mh) ? ~(unsigned)bi : 0u;
        unsigned ml = __reduce_max_sync(0xffffffffu, cd);
        if ((t & 31) == 0)
            warr[t >> 5] = ((unsigned long long)mh << 32) | ml;
        __syncthreads();

        // senders only: CTA-best over 8 warp slots, then send to cluster CTA t
        if (t < CLUSTER_) {
            unsigned long long bb = warr[0];
#pragma unroll
            for (int w = 1; w < FPS_T_ / 32; w++) {
                unsigned long long v = warr[w];
                bb = (v > bb) ? v : bb;
            }
            int g = (int)(~(unsigned)(bb & 0xffffffffu));
            int l = g - base;
            float wx = ox[l], wy = oy[l], wz = oz[l];
            unsigned a_key = smem_u32(&skey[par][rank]);
            unsigned a_cx  = smem_u32(&scx[par][rank]);
            unsigned a_cy  = smem_u32(&scy[par][rank]);
            unsigned a_cz  = smem_u32(&scz[par][rank]);
            unsigned r_key, r_cx, r_cy, r_cz;
            asm("mapa.shared::cluster.u32 %0, %1, %2;" : "=r"(r_key) : "r"(a_key), "r"(t));
            asm("mapa.shared::cluster.u32 %0, %1, %2;" : "=r"(r_cx)  : "r"(a_cx),  "r"(t));
            asm("mapa.shared::cluster.u32 %0, %1, %2;" : "=r"(r_cy)  : "r"(a_cy),  "r"(t));
            asm("mapa.shared::cluster.u32 %0, %1, %2;" : "=r"(r_cz)  : "r"(a_cz),  "r"(t));
            asm volatile("st.shared::cluster.b64 [%0], %1;" :: "r"(r_key), "l"(bb) : "memory");
            asm volatile("st.shared::cluster.b32 [%0], %1;" :: "r"(r_cx), "r"(__float_as_uint(wx)) : "memory");
            asm volatile("st.shared::cluster.b32 [%0], %1;" :: "r"(r_cy), "r"(__float_as_uint(wy)) : "memory");
            asm volatile("st.shared::cluster.b32 [%0], %1;" :: "r"(r_cz), "r"(__float_as_uint(wz)) : "memory");
        }

        // one cluster barrier per iteration (release orders the DSMEM stores)
        asm volatile("barrier.cluster.arrive.aligned;" ::: "memory");
        asm volatile("barrier.cluster.wait.aligned;" ::: "memory");

        // winner among the 8 slots (broadcast LDS; parity protects slot reuse)
        unsigned long long w0 = skey[par][0];
        int wi = 0;
#pragma unroll
        for (int r = 1; r < CLUSTER_; r++) {
            unsigned long long v = skey[par][r];
            if (v > w0) { w0 = v; wi = r; }
        }
        cx = scx[par][wi]; cy = scy[par][wi]; cz = scz[par][wi];
    }
}

// ======================= Kernel B: tiled KNN + robust centroid + features ==================
// R9 structure; scan distances computed with f32x2 packed math across center
// pairs (bit-identical to the scalar reference chain).
__global__ __launch_bounds__(256, 4) void knn_feat_kernel(float* __restrict__ out,
                                                          Perms perms)
{
    __shared__ unsigned long long cand[CTILE_][256][4];   // 32KB
    __shared__ unsigned long long heads[CTILE_][256];     // 8KB, transposed slots
    __shared__ unsigned char curs[CTILE_][256];
    __shared__ int nb[CTILE_][K_];
    __shared__ float gx[CTILE_][K_], gy[CTILE_][K_], gz[CTILE_][K_];
    __shared__ float cdv[CTILE_][SAMPLE_NUM_][3];

    const int bid = blockIdx.x;
    const int b = bid / KNN_TILES_;
    const int tile = bid % KNN_TILES_;
    const int s0 = tile * CTILE_;
    const int t = threadIdx.x;
    const float4* P = g_pts + (size_t)b * N_;

    float ccx[CTILE_], ccy[CTILE_], ccz[CTILE_], ccc[CTILE_];
#pragma unroll
    for (int c = 0; c < CTILE_; c++) {
        int bs = b * NPOINT_ + s0 + c;
        float x = g_centers[bs * 3 + 0];
        float y = g_centers[bs * 3 + 1];
        float z = g_centers[bs * 3 + 2];
        ccx[c] = x; ccy[c] = y; ccz[c] = z;
        ccc[c] = __fadd_rn(__fadd_rn(__fmul_rn(x, x), __fmul_rn(y, y)),
                           __fmul_rn(z, z));
    }
    // packed center pairs (c0,c1) and (c2,c3)
    const unsigned long long cx2a = pk2(ccx[0], ccx[1]), cx2b = pk2(ccx[2], ccx[3]);
    const unsigned long long cy2a = pk2(ccy[0], ccy[1]), cy2b = pk2(ccy[2], ccy[3]);
    const unsigned long long cz2a = pk2(ccz[0], ccz[1]), cz2b = pk2(ccz[2], ccz[3]);
    const unsigned long long cc2a = pk2(ccc[0], ccc[1]), cc2b = pk2(ccc[2], ccc[3]);
    const unsigned long long m22  = pk2(-2.0f, -2.0f);

    // exact sorted top-4 per thread per center (strict < keeps first index;
    // n ascending within thread; d2 never -0.0 under RN)
    float v0[CTILE_], v1[CTILE_], v2[CTILE_], v3[CTILE_];
    int i0[CTILE_], i1[CTILE_], i2[CTILE_], i3[CTILE_];
#pragma unroll
    for (int c = 0; c < CTILE_; c++) {
        v0[c] = v1[c] = v2[c] = v3[c] = FLT_MAX;
        i0[c] = i1[c] = i2[c] = i3[c] = 0;
    }
#pragma unroll 4
    for (int k = 0; k < 64; k++) {
        int n = t + (k << 8);
        float4 p = __ldg(&P[n]);
        const unsigned long long pxx = pk2(p.x, p.x);
        const unsigned long long pyy = pk2(p.y, p.y);
        const unsigned long long pzz = pk2(p.z, p.z);
        const unsigned long long xx2 = pk2(p.w, p.w);
        // d2 = (cc + xx) + (-2*dt): x2 mul exact, negation exact -> == reference
        unsigned long long dta = add2(add2(mul2(cx2a, pxx), mul2(cy2a, pyy)),
                                      mul2(cz2a, pzz));
        unsigned long long dtb = add2(add2(mul2(cx2b, pxx), mul2(cy2b, pyy)),
                                      mul2(cz2b, pzz));
        unsigned long long d2a = add2(add2(cc2a, xx2), mul2(dta, m22));
        unsigned long long d2b = add2(add2(cc2b, xx2), mul2(dtb, m22));
        float dv[CTILE_];
        up2(d2a, dv[0], dv[1]);
        up2(d2b, dv[2], dv[3]);
#pragma unroll
        for (int c = 0; c < CTILE_; c++) {
            float d2 = dv[c];
            if (d2 < v3[c]) {
                if (d2 < v2[c]) {
                    v3[c] = v2[c]; i3[c] = i2[c];
                    if (d2 < v1[c]) {
                        v2[c] = v1[c]; i2[c] = i1[c];
                        if (d2 < v0[c]) { v1[c] = v0[c]; i1[c] = i0[c]; v0[c] = d2; i0[c] = n; }
                        else             { v1[c] = d2; i1[c] = n; }
                    } else { v2[c] = d2; i2[c] = n; }
                } else { v3[c] = d2; i3[c] = n; }
            }
        }
    }
    auto pack = [](float v, int n) -> unsigned long long {
        unsigned fb = __float_as_uint(v);
        fb = (fb & 0x80000000u) ? ~fb : (fb | 0x80000000u);   // monotone map
        return ((unsigned long long)fb << 32) | (unsigned)n;
    };
    const int hslot = (t & 7) * 32 + (t >> 3);   // transposed heads slot
#pragma unroll
    for (int c = 0; c < CTILE_; c++) {
        unsigned long long k0 = pack(v0[c], i0[c]);
        cand[c][t][0] = k0;
        cand[c][t][1] = pack(v1[c], i1[c]);
        cand[c][t][2] = pack(v2[c], i2[c]);
        cand[c][t][3] = pack(v3[c], i3[c]);
        heads[c][hslot] = k0;
        curs[c][t] = 0;
    }
    __syncthreads();

    const int wid = t >> 5;
    const int lane = t & 31;
    if (wid < CTILE_) {
        const int c = wid;
        for (int j = 0; j < K_; j++) {
            unsigned long long lm = heads[c][lane]; int li = 0;
#pragma unroll
            for (int i = 1; i < 8; i++) {
                unsigned long long v = heads[c][i * 32 + lane];
                if (v < lm) { lm = v; li = i; }
            }
            unsigned hi = (unsigned)(lm >> 32), lo = (unsigned)lm;
            unsigned mh = __reduce_min_sync(0xffffffffu, hi);
            unsigned cl = (hi == mh) ? lo : 0xffffffffu;
            unsigned ml = __reduce_min_sync(0xffffffffu, cl);
            unsigned long long w = ((unsigned long long)mh << 32) | ml;
            if (lane == 0) nb[c][j] = (int)ml;
            if (lm == w) {                       // unique owner lane
                int T = lane * 8 + li;
                int cur = (int)curs[c][T] + 1;
                curs[c][T] = (unsigned char)cur;
                unsigned long long nh;
                if (cur < 4) {
                    nh = cand[c][T][cur];
                } else {
                    // exact refill: min key > w over T's 64 points (rare)
                    nh = 0xFFFFFFFFFFFFFFFFull;
                    for (int k = 0; k < 64; k++) {
                        int n = T + (k << 8);
                        float4 p = __ldg(&P[n]);
                        float dt = __fadd_rn(__fadd_rn(__fmul_rn(ccx[c], p.x), __fmul_rn(ccy[c], p.y)),
                                             __fmul_rn(ccz[c], p.z));
                        float d2 = __fsub_rn(__fadd_rn(ccc[c], p.w), __fmul_rn(2.0f, dt));
                        unsigned fb = __float_as_uint(d2);
                        fb = (fb & 0x80000000u) ? ~fb : (fb | 0x80000000u);
                        unsigned long long pk = ((unsigned long long)fb << 32) | (unsigned)n;
                        if (pk > w && pk < nh) nh = pk;
                    }
                }
                heads[c][li * 32 + lane] = nh;
            }
        }
        __syncwarp();

        {
            int n = nb[c][lane];
            float4 p = __ldg(&P[n]);
            gx[c][lane] = p.x; gy[c][lane] = p.y; gz[c][lane] = p.z;
        }
        __syncwarp();

        if (lane < SAMPLE_NUM_) {
            float ax = 0.f, ay = 0.f, az = 0.f;
            for (int j = 0; j < SUBSET_; j++) {
                int p = perms.p[lane][j];
                ax += gx[c][p]; ay += gy[c][p]; az += gz[c][p];
            }
            cdv[c][lane][0] = ax / (float)SUBSET_;
            cdv[c][lane][1] = ay / (float)SUBSET_;
            cdv[c][lane][2] = az / (float)SUBSET_;
        }
        __syncwarp();

        if (lane == 0) {
            float sq[SAMPLE_NUM_], ps[SAMPLE_NUM_];
            for (int j = 0; j < SAMPLE_NUM_; j++)
                sq[j] = cdv[c][j][0] * cdv[c][j][0] + cdv[c][j][1] * cdv[c][j][1]
                      + cdv[c][j][2] * cdv[c][j][2];
            for (int j = 0; j < SAMPLE_NUM_; j++) {
                float acc = 0.f;
                for (int k2 = 0; k2 < SAMPLE_NUM_; k2++) {
                    float dt = cdv[c][j][0] * cdv[c][k2][0] + cdv[c][j][1] * cdv[c][k2][1]
                             + cdv[c][j][2] * cdv[c][k2][2];
                    acc += sq[j] + sq[k2] - 2.0f * dt;
                }
                ps[j] = acc;
            }
            bool used[SAMPLE_NUM_];
            for (int j = 0; j < SAMPLE_NUM_; j++) used[j] = false;
            float mx = 0.f, my = 0.f, mz = 0.f;
            for (int r = 0; r < SEL_; r++) {
                int bsel = 0; float bv = FLT_MAX;
                for (int k2 = 0; k2 < SAMPLE_NUM_; k2++)
                    if (!used[k2] && ps[k2] < bv) { bv = ps[k2]; bsel = k2; }
                used[bsel] = true;
                mx += cdv[c][bsel][0]; my += cdv[c][bsel][1]; mz += cdv[c][bsel][2];
            }
            mx /= (float)SEL_; my /= (float)SEL_; mz /= (float)SEL_;

            float cx = ccx[c], cy = ccy[c], cz = ccz[c];
            float ref_norm = sqrtf(cx * cx + cy * cy + cz * cz);
            float den = ref_norm + 1e-4f;
            float ux = cx / den, uy = cy / den, uz = cz / den;
            float ix = RADIUS_ * ux + cx, iy = RADIUS_ * uy + cy, iz = RADIUS_ * uz + cz;

            float crx = cx - mx, cry = cy - my, crz = cz - mz;
            float crd = sqrtf(crx * crx + cry * cry + crz * crz);
            float cvx = ix - mx, cvy = iy - my, cvz = iz - mz;
            float cid = sqrtf(cvx * cvx + cvy * cvy + cvz * cvz);
            float dot = crx * cvx + cry * cvy + crz * cvz;
            float ang_rci = dot / (crd * cid + 1e-6f);

            float irx = cx - ix, iry = cy - iy, irz = cz - iz;
            float icx = mx - ix, icy = my - iy, icz = mz - iz;
            float dot2 = irx * icx + iry * icy + irz * icz;
            float ang_ric = dot2 / (RADIUS_ * cid + 1e-6f);

            int bs = b * NPOINT_ + s0 + c;
            float* o = out + (size_t)bs * 5;
            o[0] = ref_norm; o[1] = crd; o[2] = cid; o[3] = ang_rci; o[4] = ang_ric;
        }
    }
}

// ======================= Host: threefry-2x32 (JAX partitionable PRNG) =======================
static inline uint32_t rotl32_(uint32_t x, int r) { return (x << r) | (x >> (32 - r)); }

static void tf2x32_(uint32_t k0, uint32_t k1, uint32_t x0, uint32_t x1,
                    uint32_t& o0, uint32_t& o1)
{
    static const int R0[4] = {13, 15, 26, 6};
    static const int R1[4] = {17, 29, 16, 24};
    uint32_t ks[3] = {k0, k1, k0 ^ k1 ^ 0x1BD11BDAu};
    x0 += ks[0]; x1 += ks[1];
    for (int i = 0; i < 5; i++) {
        const int* R = (i & 1) ? R1 : R0;
        for (int j = 0; j < 4; j++) { x0 += x1; x1 = rotl32_(x1, R[j]); x1 ^= x0; }
        x0 += ks[(i + 1) % 3];
        x1 += ks[(i + 2) % 3] + (uint32_t)(i + 1);
    }
    o0 = x0; o1 = x1;
}

// jax.random.permutation(fold_in(key(42), i), 32)[:29], threefry partitionable mode.
static void make_perms(unsigned char p[SAMPLE_NUM_][SUBSET_])
{
    for (int i = 0; i < SAMPLE_NUM_; i++) {
        uint32_t k0, k1, s0, s1;
        tf2x32_(0u, 42u, 0u, (uint32_t)i, k0, k1);     // fold_in
        tf2x32_(k0, k1, 0u, 1u, s0, s1);               // split -> subkey (index 1)
        uint32_t bits[K_];
        for (int j = 0; j < K_; j++) {
            uint32_t hi, lo;
            tf2x32_(s0, s1, 0u, (uint32_t)j, hi, lo);
            bits[j] = hi ^ lo;                         // 32-bit path XORs both words
        }
        int idx[K_];
        for (int j = 0; j < K_; j++) idx[j] = j;
        for (int a = 1; a < K_; a++) {                 // stable insertion sort
            uint32_t bv = bits[a]; int iv = idx[a]; int c = a - 1;
            while (c >= 0 && bits[c] > bv) {
                bits[c + 1] = bits[c]; idx[c + 1] = idx[c]; c--;
            }
            bits[c + 1] = bv; idx[c + 1] = iv;
        }
        for (int j = 0; j < SUBSET_; j++) p[i][j] = (unsigned char)idx[j];
    }
}

extern "C" void kernel_launch(void* const* d_in, const int* in_sizes, int n_in,
                              void* d_out, int out_size)
{
    (void)in_sizes; (void)n_in; (void)out_size;
    const float* xyz = (const float*)d_in[0];
    float* out = (float*)d_out;

    Perms perms;
    make_perms(perms.p);   // deterministic, cheap, every call

    fps_cluster_kernel<<<B_ * CLUSTER_, FPS_T_>>>(xyz);
    knn_feat_kernel<<<B_ * KNN_TILES_, 256>>>(out, perms);
}